// round 11
// baseline (speedup 1.0000x reference)
#include <cuda_runtime.h>
#include <cuda_fp16.h>

#define BB 4
#define MM 128
#define LL 512
#define DD 768

#define LSPLIT 6
#define LMAX   86
#define CH     22           // l per pipeline chunk (4 chunks)
#define APADU  132          // u32 row stride for sh_a (16B-aligned rows)
#define NEGH   0xFC00FC00u  // fp16x2 (-inf,-inf)

// fp16 partials [LSPLIT][B][M][D] = 4.7 MB static scratch (no allocs)
__device__ unsigned short g_scratch[LSPLIT * BB * MM * DD];

#define SH_A_U32   (LMAX * APADU)            // 11352
#define SH_HBUF    (CH * 64)                 // 1408 u32 per buffer
#define SMEM_BYTES ((SH_A_U32 + 2 * SH_HBUF) * (int)sizeof(unsigned int))  // ~56.6 KB

__global__ __launch_bounds__(512, 1)
void mr_main(const float* __restrict__ h, const int* __restrict__ mask)
{
    extern __shared__ unsigned int smbuf[];
    unsigned int* sh_a = smbuf;                 // [86][APADU] additive splat
    unsigned int* sh_h = smbuf + SH_A_U32;      // 2 x [22][64] fp16x2 (128 d)

    const int b    = blockIdx.z;
    const int d0   = blockIdx.x * 128;
    const int sp   = blockIdx.y;
    const int l0   = sp * 85 + (sp < 2 ? sp : 2);
    const int llen = 85 + (sp < 2 ? 1 : 0);

    const int tid  = threadIdx.x;
    const int lane = tid & 31;
    const int w    = tid >> 5;            // 16 warps; warp w -> m rows [8w, 8w+8)

    const float4* hg = (const float4*)h + ((size_t)b * LL + l0) * (DD / 4) + (d0 >> 2);

    // ---- prefetch h chunk 0 into regs (issued before mask staging) ----
    float4 ph0 = make_float4(0.f,0.f,0.f,0.f), ph1 = ph0;
    {
        const int n4 = CH * 32;                       // 704
        const int i0 = tid, i1 = 512 + tid;
        if (i0 < n4) ph0 = hg[(size_t)(i0 >> 5) * (DD / 4) + (i0 & 31)];
        if (i1 < n4) ph1 = hg[(size_t)(i1 >> 5) * (DD / 4) + (i1 & 31)];
    }
    // ---- stage full mask transposed [l][m]; LDG coalesced over l ----
    for (int m = w; m < MM; m += 16) {
        const int* mg = mask + ((size_t)b * MM + m) * LL + l0;
        for (int lb = lane; lb < llen; lb += 32)
            sh_a[lb * APADU + m] = mg[lb] ? 0u : NEGH;
    }
    // ---- STS chunk 0 ----
    {
        const int n4 = CH * 32;
        const int i0 = tid, i1 = 512 + tid;
        if (i0 < n4) {
            const half2 p0 = __float22half2_rn(make_float2(ph0.x, ph0.y));
            const half2 p1 = __float22half2_rn(make_float2(ph0.z, ph0.w));
            uint2 o; o.x = *(const unsigned int*)&p0; o.y = *(const unsigned int*)&p1;
            *(uint2*)&sh_h[(i0 >> 5) * 64 + (i0 & 31) * 2] = o;
        }
        if (i1 < n4) {
            const half2 p0 = __float22half2_rn(make_float2(ph1.x, ph1.y));
            const half2 p1 = __float22half2_rn(make_float2(ph1.z, ph1.w));
            uint2 o; o.x = *(const unsigned int*)&p0; o.y = *(const unsigned int*)&p1;
            *(uint2*)&sh_h[(i1 >> 5) * 64 + (i1 & 31) * 2] = o;
        }
    }
    __syncthreads();

    // ---- pipelined accumulate: 8 m x 128 d (fp16x2) per warp ----
    const unsigned int ninf = NEGH;
    const half2 hninf = *(const half2*)&ninf;
    half2 acc[8][2];
#pragma unroll
    for (int i = 0; i < 8; ++i) { acc[i][0] = hninf; acc[i][1] = hninf; }

    const int mb = w * 8;
    const int nch = (llen + CH - 1) / CH;         // 4

    for (int c = 0; c < nch; ++c) {
        const int cl0 = c * CH;
        const int len = min(CH, llen - cl0);
        unsigned int* cur = sh_h + (c & 1) * SH_HBUF;

        // prefetch next chunk into regs (overlaps with compute below)
        float4 qh0, qh1; int nn4 = 0;
        if (c + 1 < nch) {
            const int nl0 = cl0 + CH;
            nn4 = min(CH, llen - nl0) * 32;
            const int i0 = tid, i1 = 512 + tid;
            if (i0 < nn4) qh0 = hg[(size_t)(nl0 + (i0 >> 5)) * (DD / 4) + (i0 & 31)];
            if (i1 < nn4) qh1 = hg[(size_t)(nl0 + (i1 >> 5)) * (DD / 4) + (i1 & 31)];
        }

        // compute chunk c (2 l per iter, loads batched)
        int l = 0;
        for (; l + 2 <= len; l += 2) {
            const uint2 hva = *(const uint2*)&cur[(l + 0) * 64 + lane * 2];
            const uint2 hvb = *(const uint2*)&cur[(l + 1) * 64 + lane * 2];
            const uint4 a0  = *(const uint4*)&sh_a[(cl0 + l + 0) * APADU + mb];
            const uint4 a1  = *(const uint4*)&sh_a[(cl0 + l + 0) * APADU + mb + 4];
            const uint4 b0  = *(const uint4*)&sh_a[(cl0 + l + 1) * APADU + mb];
            const uint4 b1  = *(const uint4*)&sh_a[(cl0 + l + 1) * APADU + mb + 4];

            const half2 ha0 = *(const half2*)&hva.x, ha1 = *(const half2*)&hva.y;
            const half2 hb0 = *(const half2*)&hvb.x, hb1 = *(const half2*)&hvb.y;
            const unsigned int av[8] = {a0.x,a0.y,a0.z,a0.w, a1.x,a1.y,a1.z,a1.w};
            const unsigned int bv[8] = {b0.x,b0.y,b0.z,b0.w, b1.x,b1.y,b1.z,b1.w};
#pragma unroll
            for (int i = 0; i < 8; ++i) {
                const half2 aa = *(const half2*)&av[i];
                const half2 ab = *(const half2*)&bv[i];
                acc[i][0] = __hmax2(__hmax2(acc[i][0], __hadd2(ha0, aa)), __hadd2(hb0, ab));
                acc[i][1] = __hmax2(__hmax2(acc[i][1], __hadd2(ha1, aa)), __hadd2(hb1, ab));
            }
        }
        if (l < len) {
            const uint2 hv = *(const uint2*)&cur[l * 64 + lane * 2];
            const uint4 a0 = *(const uint4*)&sh_a[(cl0 + l) * APADU + mb];
            const uint4 a1 = *(const uint4*)&sh_a[(cl0 + l) * APADU + mb + 4];
            const half2 h0 = *(const half2*)&hv.x, h1 = *(const half2*)&hv.y;
            const unsigned int av[8] = {a0.x,a0.y,a0.z,a0.w, a1.x,a1.y,a1.z,a1.w};
#pragma unroll
            for (int i = 0; i < 8; ++i) {
                const half2 a = *(const half2*)&av[i];
                acc[i][0] = __hmax2(acc[i][0], __hadd2(h0, a));
                acc[i][1] = __hmax2(acc[i][1], __hadd2(h1, a));
            }
        }

        // STS next chunk into the other buffer, then barrier
        if (c + 1 < nch) {
            unsigned int* nxt = sh_h + ((c + 1) & 1) * SH_HBUF;
            const int i0 = tid, i1 = 512 + tid;
            if (i0 < nn4) {
                const half2 p0 = __float22half2_rn(make_float2(qh0.x, qh0.y));
                const half2 p1 = __float22half2_rn(make_float2(qh0.z, qh0.w));
                uint2 o; o.x = *(const unsigned int*)&p0; o.y = *(const unsigned int*)&p1;
                *(uint2*)&nxt[(i0 >> 5) * 64 + (i0 & 31) * 2] = o;
            }
            if (i1 < nn4) {
                const half2 p0 = __float22half2_rn(make_float2(qh1.x, qh1.y));
                const half2 p1 = __float22half2_rn(make_float2(qh1.z, qh1.w));
                uint2 o; o.x = *(const unsigned int*)&p0; o.y = *(const unsigned int*)&p1;
                *(uint2*)&nxt[(i1 >> 5) * 64 + (i1 & 31) * 2] = o;
            }
            __syncthreads();
        }
    }

    // ---- write fp16 partials [sp][b][m][d], coalesced 8B/thread ----
    unsigned short* op = g_scratch + (((size_t)sp * BB + b) * MM + mb) * DD + d0 + lane * 4;
#pragma unroll
    for (int i = 0; i < 8; ++i) {
        uint2 o;
        o.x = *(const unsigned int*)&acc[i][0];
        o.y = *(const unsigned int*)&acc[i][1];
        *(uint2*)(op + (size_t)i * DD) = o;
    }
}

#define TOTU4 (BB * MM * DD / 8)    // 49152 uint4 (8 fp16 each)

__global__ __launch_bounds__(256, 1)
void mr_combine(float* __restrict__ out)
{
    const int t = blockIdx.x * 256 + threadIdx.x;    // 0..49151
    const uint4* s = (const uint4*)g_scratch;

    uint4 v[LSPLIT];
#pragma unroll
    for (int sp = 0; sp < LSPLIT; ++sp)              // MLP 6 x LDG.128
        v[sp] = s[(size_t)sp * TOTU4 + t];

    half2 r0 = *(const half2*)&v[0].x;
    half2 r1 = *(const half2*)&v[0].y;
    half2 r2 = *(const half2*)&v[0].z;
    half2 r3 = *(const half2*)&v[0].w;
#pragma unroll
    for (int sp = 1; sp < LSPLIT; ++sp) {
        r0 = __hmax2(r0, *(const half2*)&v[sp].x);
        r1 = __hmax2(r1, *(const half2*)&v[sp].y);
        r2 = __hmax2(r2, *(const half2*)&v[sp].z);
        r3 = __hmax2(r3, *(const half2*)&v[sp].w);
    }
    const float2 f0 = __half22float2(r0);
    const float2 f1 = __half22float2(r1);
    const float2 f2 = __half22float2(r2);
    const float2 f3 = __half22float2(r3);
    float4 o0, o1;
    o0.x = f0.x; o0.y = f0.y; o0.z = f1.x; o0.w = f1.y;
    o1.x = f2.x; o1.y = f2.y; o1.z = f3.x; o1.w = f3.y;
    float4* og = (float4*)out + (size_t)t * 2;
    og[0] = o0;
    og[1] = o1;
}

extern "C" void kernel_launch(void* const* d_in, const int* in_sizes, int n_in,
                              void* d_out, int out_size)
{
    const float* h    = (const float*)d_in[0];
    const int*   mask = (const int*)  d_in[1];
    float*       out  = (float*)d_out;

    cudaFuncSetAttribute(mr_main,
                         cudaFuncAttributeMaxDynamicSharedMemorySize, SMEM_BYTES);

    dim3 grid(DD / 128, LSPLIT, BB);      // 6 x 6 x 4 = 144 blocks, occ 1
    mr_main<<<grid, 512, SMEM_BYTES>>>(h, mask);
    mr_combine<<<TOTU4 / 256, 256>>>(out);   // 192 blocks
}

// round 12
// speedup vs baseline: 1.1085x; 1.1085x over previous
#include <cuda_runtime.h>
#include <cuda_fp16.h>

#define BB 4
#define MM 128
#define LL 512
#define DD 768

#define LSPLIT 6
#define LMAX   86
#define APADU  132          // u32 row stride for sh_a (16B-aligned rows)
#define NEGH   0xFC00FC00u  // fp16x2 (-inf,-inf)

// fp16 partials [LSPLIT][B][M][D] = 4.7 MB static scratch (no allocs)
__device__ unsigned short g_scratch[LSPLIT * BB * MM * DD];

#define SH_H_U32   (LMAX * 64)
#define SMEM_BYTES ((SH_H_U32 + LMAX * APADU) * (int)sizeof(unsigned int))  // ~66 KB

__global__ __launch_bounds__(512, 1)
void mr_main(const float* __restrict__ h, const int* __restrict__ mask)
{
    extern __shared__ unsigned int sm[];
    unsigned int* sh_h = sm;              // [l][64] fp16x2 (128 d)
    unsigned int* sh_a = sm + SH_H_U32;   // [l][APADU] additive splat (0 or -inf,-inf)

    const int b    = blockIdx.z;
    const int d0   = blockIdx.x * 128;
    const int sp   = blockIdx.y;
    const int l0   = sp * 85 + (sp < 2 ? sp : 2);
    const int llen = 85 + (sp < 2 ? 1 : 0);

    const int tid  = threadIdx.x;
    const int lane = tid & 31;
    const int w    = tid >> 5;            // 16 warps; warp w -> m rows [8w, 8w+8)

    // ---- stage h tile: coalesced float4 LDG -> fp16x2 -> STS ----
    {
        const float4* hg = (const float4*)h + ((size_t)b * LL + l0) * (DD / 4) + (d0 >> 2);
        const int n = llen * 32;
        for (int idx = tid; idx < n; idx += 512) {
            const int l = idx >> 5, q = idx & 31;
            const float4 v = hg[(size_t)l * (DD / 4) + q];
            const half2 p0 = __float22half2_rn(make_float2(v.x, v.y));
            const half2 p1 = __float22half2_rn(make_float2(v.z, v.w));
            uint2 o; o.x = *(const unsigned int*)&p0; o.y = *(const unsigned int*)&p1;
            *(uint2*)&sh_h[l * 64 + q * 2] = o;
        }
    }
    // ---- stage mask transposed [l][m]; LDG coalesced over l ----
    for (int m = w; m < MM; m += 16) {
        const int* mg = mask + ((size_t)b * MM + m) * LL + l0;
        for (int lb = lane; lb < llen; lb += 32)
            sh_a[lb * APADU + m] = mg[lb] ? 0u : NEGH;
    }
    __syncthreads();

    // ---- accumulate: 8 m x 128 d (fp16x2) per warp; 2 l per iter, loads batched ----
    const unsigned int ninf = NEGH;
    const half2 hninf = *(const half2*)&ninf;
    half2 acc[8][2];
#pragma unroll
    for (int i = 0; i < 8; ++i) { acc[i][0] = hninf; acc[i][1] = hninf; }

    const int mb = w * 8;
    int l = 0;
#pragma unroll 2
    for (; l + 2 <= llen; l += 2) {
        // 6 independent LDS up-front
        const uint2 hva = *(const uint2*)&sh_h[(l + 0) * 64 + lane * 2];
        const uint2 hvb = *(const uint2*)&sh_h[(l + 1) * 64 + lane * 2];
        const uint4 a0  = *(const uint4*)&sh_a[(l + 0) * APADU + mb];
        const uint4 a1  = *(const uint4*)&sh_a[(l + 0) * APADU + mb + 4];
        const uint4 b0  = *(const uint4*)&sh_a[(l + 1) * APADU + mb];
        const uint4 b1  = *(const uint4*)&sh_a[(l + 1) * APADU + mb + 4];

        const half2 ha0 = *(const half2*)&hva.x, ha1 = *(const half2*)&hva.y;
        const half2 hb0 = *(const half2*)&hvb.x, hb1 = *(const half2*)&hvb.y;
        const unsigned int av[8] = {a0.x,a0.y,a0.z,a0.w, a1.x,a1.y,a1.z,a1.w};
        const unsigned int bv[8] = {b0.x,b0.y,b0.z,b0.w, b1.x,b1.y,b1.z,b1.w};
#pragma unroll
        for (int i = 0; i < 8; ++i) {
            const half2 aa = *(const half2*)&av[i];
            const half2 ab = *(const half2*)&bv[i];
            acc[i][0] = __hmax2(__hmax2(acc[i][0], __hadd2(ha0, aa)), __hadd2(hb0, ab));
            acc[i][1] = __hmax2(__hmax2(acc[i][1], __hadd2(ha1, aa)), __hadd2(hb1, ab));
        }
    }
    if (l < llen) {   // tail (llen odd: 85)
        const uint2 hv = *(const uint2*)&sh_h[l * 64 + lane * 2];
        const uint4 a0 = *(const uint4*)&sh_a[l * APADU + mb];
        const uint4 a1 = *(const uint4*)&sh_a[l * APADU + mb + 4];
        const half2 h0 = *(const half2*)&hv.x, h1 = *(const half2*)&hv.y;
        const unsigned int av[8] = {a0.x,a0.y,a0.z,a0.w, a1.x,a1.y,a1.z,a1.w};
#pragma unroll
        for (int i = 0; i < 8; ++i) {
            const half2 a = *(const half2*)&av[i];
            acc[i][0] = __hmax2(acc[i][0], __hadd2(h0, a));
            acc[i][1] = __hmax2(acc[i][1], __hadd2(h1, a));
        }
    }

    // ---- write fp16 partials [sp][b][m][d], coalesced 8B/thread ----
    unsigned short* op = g_scratch + (((size_t)sp * BB + b) * MM + mb) * DD + d0 + lane * 4;
#pragma unroll
    for (int i = 0; i < 8; ++i) {
        uint2 o;
        o.x = *(const unsigned int*)&acc[i][0];
        o.y = *(const unsigned int*)&acc[i][1];
        *(uint2*)(op + (size_t)i * DD) = o;
    }
}

#define TOTU4 (BB * MM * DD / 8)    // 49152 uint4 (8 fp16 each)

__global__ __launch_bounds__(512, 1)
void mr_combine(float* __restrict__ out)
{
    const int t = blockIdx.x * 512 + threadIdx.x;    // 0..49151, single wave (96 blocks)
    const uint4* s = (const uint4*)g_scratch;

    uint4 v[LSPLIT];
#pragma unroll
    for (int sp = 0; sp < LSPLIT; ++sp)              // MLP 6 x LDG.128
        v[sp] = s[(size_t)sp * TOTU4 + t];

    half2 r0 = *(const half2*)&v[0].x;
    half2 r1 = *(const half2*)&v[0].y;
    half2 r2 = *(const half2*)&v[0].z;
    half2 r3 = *(const half2*)&v[0].w;
#pragma unroll
    for (int sp = 1; sp < LSPLIT; ++sp) {
        r0 = __hmax2(r0, *(const half2*)&v[sp].x);
        r1 = __hmax2(r1, *(const half2*)&v[sp].y);
        r2 = __hmax2(r2, *(const half2*)&v[sp].z);
        r3 = __hmax2(r3, *(const half2*)&v[sp].w);
    }
    const float2 f0 = __half22float2(r0);
    const float2 f1 = __half22float2(r1);
    const float2 f2 = __half22float2(r2);
    const float2 f3 = __half22float2(r3);
    float4 o0, o1;
    o0.x = f0.x; o0.y = f0.y; o0.z = f1.x; o0.w = f1.y;
    o1.x = f2.x; o1.y = f2.y; o1.z = f3.x; o1.w = f3.y;
    float4* og = (float4*)out + (size_t)t * 2;
    og[0] = o0;
    og[1] = o1;
}

extern "C" void kernel_launch(void* const* d_in, const int* in_sizes, int n_in,
                              void* d_out, int out_size)
{
    const float* h    = (const float*)d_in[0];
    const int*   mask = (const int*)  d_in[1];
    float*       out  = (float*)d_out;

    cudaFuncSetAttribute(mr_main,
                         cudaFuncAttributeMaxDynamicSharedMemorySize, SMEM_BYTES);

    dim3 grid(DD / 128, LSPLIT, BB);      // 6 x 6 x 4 = 144 blocks, occ 1
    mr_main<<<grid, 512, SMEM_BYTES>>>(h, mask);
    mr_combine<<<TOTU4 / 512, 512>>>(out);   // 96 blocks = exactly 1 wave
}

// round 13
// speedup vs baseline: 1.1235x; 1.0135x over previous
#include <cuda_runtime.h>
#include <cuda_fp16.h>

#define BB 4
#define MM 128
#define LL 512
#define DD 768

#define LSPLIT 12
#define LMAX   43
#define APADU  132          // u32 row stride for sh_a (16B-aligned rows)
#define NEGH   0xFC00FC00u  // fp16x2 (-inf,-inf)

// fp16 partials [LSPLIT][B][M][D] = 9.4 MB static scratch (no allocs)
__device__ unsigned short g_scratch[LSPLIT * BB * MM * DD];

#define SH_H_U32   (LMAX * 128)                  // [l][128] fp16x2 = 256 d
#define SMEM_BYTES ((SH_H_U32 + LMAX * APADU) * (int)sizeof(unsigned int))  // ~44.7 KB

__global__ __launch_bounds__(512, 1)
void mr_main(const float* __restrict__ h, const int* __restrict__ mask)
{
    extern __shared__ unsigned int sm[];
    unsigned int* sh_h = sm;              // [l][128] fp16x2 (256 d)
    unsigned int* sh_a = sm + SH_H_U32;   // [l][APADU] additive splat (0 or -inf,-inf)

    const int b    = blockIdx.z;
    const int d0   = blockIdx.x * 256;                 // 3 d-tiles
    const int sp   = blockIdx.y;                       // 12 l-splits
    const int l0   = sp * 42 + (sp < 8 ? sp : 8);      // 8x43 + 4x42 = 512
    const int llen = 42 + (sp < 8 ? 1 : 0);

    const int tid  = threadIdx.x;
    const int lane = tid & 31;
    const int w    = tid >> 5;            // 16 warps; warp w -> m rows [8w, 8w+8)

    // ---- stage h tile [llen][256 d]: coalesced float4 LDG -> fp16x2 -> STS ----
    {
        const float4* hg = (const float4*)h + ((size_t)b * LL + l0) * (DD / 4) + (d0 >> 2);
        const int n = llen * 64;                        // float4 per tile
        for (int idx = tid; idx < n; idx += 512) {
            const int l = idx >> 6, q = idx & 63;
            const float4 v = hg[(size_t)l * (DD / 4) + q];
            const half2 p0 = __float22half2_rn(make_float2(v.x, v.y));
            const half2 p1 = __float22half2_rn(make_float2(v.z, v.w));
            uint2 o; o.x = *(const unsigned int*)&p0; o.y = *(const unsigned int*)&p1;
            *(uint2*)&sh_h[l * 128 + q * 2] = o;
        }
    }
    // ---- stage mask transposed [l][m]; LDG coalesced over l ----
    for (int m = w; m < MM; m += 16) {
        const int* mg = mask + ((size_t)b * MM + m) * LL + l0;
        for (int lb = lane; lb < llen; lb += 32)
            sh_a[lb * APADU + m] = mg[lb] ? 0u : NEGH;
    }
    __syncthreads();

    // ---- accumulate: 8 m x 256 d (fp16x2) per warp; 1 l per iter, 3 loads + 64 math ----
    const unsigned int ninf = NEGH;
    const half2 hninf = *(const half2*)&ninf;
    half2 acc[8][4];
#pragma unroll
    for (int i = 0; i < 8; ++i)
#pragma unroll
        for (int j = 0; j < 4; ++j)
            acc[i][j] = hninf;

    const int mb = w * 8;
    for (int l = 0; l < llen; ++l) {
        const uint4 hv = *(const uint4*)&sh_h[l * 128 + lane * 4];   // 8 d
        const uint4 a0 = *(const uint4*)&sh_a[l * APADU + mb];       // uniform -> broadcast
        const uint4 a1 = *(const uint4*)&sh_a[l * APADU + mb + 4];

        const half2 h0 = *(const half2*)&hv.x;
        const half2 h1 = *(const half2*)&hv.y;
        const half2 h2 = *(const half2*)&hv.z;
        const half2 h3 = *(const half2*)&hv.w;
        const unsigned int av[8] = {a0.x,a0.y,a0.z,a0.w, a1.x,a1.y,a1.z,a1.w};
#pragma unroll
        for (int i = 0; i < 8; ++i) {
            const half2 a = *(const half2*)&av[i];
            acc[i][0] = __hmax2(acc[i][0], __hadd2(h0, a));
            acc[i][1] = __hmax2(acc[i][1], __hadd2(h1, a));
            acc[i][2] = __hmax2(acc[i][2], __hadd2(h2, a));
            acc[i][3] = __hmax2(acc[i][3], __hadd2(h3, a));
        }
    }

    // ---- write fp16 partials [sp][b][m][d], coalesced 16B/thread ----
    unsigned short* op = g_scratch + (((size_t)sp * BB + b) * MM + mb) * DD + d0 + lane * 8;
#pragma unroll
    for (int i = 0; i < 8; ++i) {
        uint4 o;
        o.x = *(const unsigned int*)&acc[i][0];
        o.y = *(const unsigned int*)&acc[i][1];
        o.z = *(const unsigned int*)&acc[i][2];
        o.w = *(const unsigned int*)&acc[i][3];
        *(uint4*)(op + (size_t)i * DD) = o;
    }
}

#define TOTU4 (BB * MM * DD / 8)    // 49152 uint4 (8 fp16 each)

__global__ __launch_bounds__(256, 1)
void mr_combine(float* __restrict__ out)
{
    const int t = blockIdx.x * 256 + threadIdx.x;    // 0..49151
    const uint4* s = (const uint4*)g_scratch;

    uint4 v[LSPLIT];
#pragma unroll
    for (int sp = 0; sp < LSPLIT; ++sp)              // MLP 12 x LDG.128
        v[sp] = s[(size_t)sp * TOTU4 + t];

    half2 r0 = *(const half2*)&v[0].x;
    half2 r1 = *(const half2*)&v[0].y;
    half2 r2 = *(const half2*)&v[0].z;
    half2 r3 = *(const half2*)&v[0].w;
#pragma unroll
    for (int sp = 1; sp < LSPLIT; ++sp) {
        r0 = __hmax2(r0, *(const half2*)&v[sp].x);
        r1 = __hmax2(r1, *(const half2*)&v[sp].y);
        r2 = __hmax2(r2, *(const half2*)&v[sp].z);
        r3 = __hmax2(r3, *(const half2*)&v[sp].w);
    }
    const float2 f0 = __half22float2(r0);
    const float2 f1 = __half22float2(r1);
    const float2 f2 = __half22float2(r2);
    const float2 f3 = __half22float2(r3);
    float4 o0, o1;
    o0.x = f0.x; o0.y = f0.y; o0.z = f1.x; o0.w = f1.y;
    o1.x = f2.x; o1.y = f2.y; o1.z = f3.x; o1.w = f3.y;
    float4* og = (float4*)out + (size_t)t * 2;
    og[0] = o0;
    og[1] = o1;
}

extern "C" void kernel_launch(void* const* d_in, const int* in_sizes, int n_in,
                              void* d_out, int out_size)
{
    const float* h    = (const float*)d_in[0];
    const int*   mask = (const int*)  d_in[1];
    float*       out  = (float*)d_out;

    cudaFuncSetAttribute(mr_main,
                         cudaFuncAttributeMaxDynamicSharedMemorySize, SMEM_BYTES);

    dim3 grid(DD / 256, LSPLIT, BB);      // 3 x 12 x 4 = 144 blocks, occ 1
    mr_main<<<grid, 512, SMEM_BYTES>>>(h, mask);
    mr_combine<<<TOTU4 / 256, 256>>>(out);   // 192 blocks
}

// round 14
// speedup vs baseline: 1.2600x; 1.1214x over previous
#include <cuda_runtime.h>
#include <cuda_fp16.h>

#define BB 4
#define MM 128
#define LL 512
#define DD 768

#define LSPLIT 6
#define LMAX   86
#define APADU  68           // u32 row stride for sh_a (64 m + pad, 16B-aligned)
#define NEGH   0xFC00FC00u  // fp16x2 (-inf,-inf)

// fp16 partials [LSPLIT][B][M][D] = 4.7 MB static scratch (no allocs)
__device__ unsigned short g_scratch[LSPLIT * BB * MM * DD];

#define SH_H_U32   (LMAX * 64)
#define SMEM_BYTES ((SH_H_U32 + LMAX * APADU) * (int)sizeof(unsigned int))  // ~45.4 KB

__global__ __launch_bounds__(256)
void mr_main(const float* __restrict__ h, const int* __restrict__ mask)
{
    extern __shared__ unsigned int sm[];
    unsigned int* sh_h = sm;              // [l][64] fp16x2 (128 d)
    unsigned int* sh_a = sm + SH_H_U32;   // [l][APADU] additive splat (0 or -inf,-inf)

    const int b    = blockIdx.z;
    const int d0   = blockIdx.x * 128;
    const int sp   = blockIdx.y >> 1;
    const int m0   = (blockIdx.y & 1) * 64;            // m-half
    const int l0   = sp * 85 + (sp < 2 ? sp : 2);
    const int llen = 85 + (sp < 2 ? 1 : 0);

    const int tid  = threadIdx.x;
    const int lane = tid & 31;
    const int w    = tid >> 5;            // 8 warps; warp w -> m rows [m0+8w, m0+8w+8)

    // ---- stage h tile: coalesced float4 LDG -> fp16x2 -> STS ----
    {
        const float4* hg = (const float4*)h + ((size_t)b * LL + l0) * (DD / 4) + (d0 >> 2);
        const int n = llen * 32;
        for (int idx = tid; idx < n; idx += 256) {
            const int l = idx >> 5, q = idx & 31;
            const float4 v = hg[(size_t)l * (DD / 4) + q];
            const half2 p0 = __float22half2_rn(make_float2(v.x, v.y));
            const half2 p1 = __float22half2_rn(make_float2(v.z, v.w));
            uint2 o; o.x = *(const unsigned int*)&p0; o.y = *(const unsigned int*)&p1;
            *(uint2*)&sh_h[l * 64 + q * 2] = o;
        }
    }
    // ---- stage mask transposed [l][m] (64 m); LDG coalesced over l ----
    for (int m = w; m < 64; m += 8) {
        const int* mg = mask + ((size_t)b * MM + m0 + m) * LL + l0;
        for (int lb = lane; lb < llen; lb += 32)
            sh_a[lb * APADU + m] = mg[lb] ? 0u : NEGH;
    }
    __syncthreads();

    // ---- accumulate: 8 m x 128 d (fp16x2) per warp; 2 l per iter, loads batched ----
    const unsigned int ninf = NEGH;
    const half2 hninf = *(const half2*)&ninf;
    half2 acc[8][2];
#pragma unroll
    for (int i = 0; i < 8; ++i) { acc[i][0] = hninf; acc[i][1] = hninf; }

    const int mb = w * 8;
    int l = 0;
    for (; l + 2 <= llen; l += 2) {
        // 6 independent LDS up-front
        const uint2 hva = *(const uint2*)&sh_h[(l + 0) * 64 + lane * 2];
        const uint2 hvb = *(const uint2*)&sh_h[(l + 1) * 64 + lane * 2];
        const uint4 a0  = *(const uint4*)&sh_a[(l + 0) * APADU + mb];
        const uint4 a1  = *(const uint4*)&sh_a[(l + 0) * APADU + mb + 4];
        const uint4 b0  = *(const uint4*)&sh_a[(l + 1) * APADU + mb];
        const uint4 b1  = *(const uint4*)&sh_a[(l + 1) * APADU + mb + 4];

        const half2 ha0 = *(const half2*)&hva.x, ha1 = *(const half2*)&hva.y;
        const half2 hb0 = *(const half2*)&hvb.x, hb1 = *(const half2*)&hvb.y;
        const unsigned int av[8] = {a0.x,a0.y,a0.z,a0.w, a1.x,a1.y,a1.z,a1.w};
        const unsigned int bv[8] = {b0.x,b0.y,b0.z,b0.w, b1.x,b1.y,b1.z,b1.w};
#pragma unroll
        for (int i = 0; i < 8; ++i) {
            const half2 aa = *(const half2*)&av[i];
            const half2 ab = *(const half2*)&bv[i];
            acc[i][0] = __hmax2(__hmax2(acc[i][0], __hadd2(ha0, aa)), __hadd2(hb0, ab));
            acc[i][1] = __hmax2(__hmax2(acc[i][1], __hadd2(ha1, aa)), __hadd2(hb1, ab));
        }
    }
    if (l < llen) {   // tail (llen odd: 85)
        const uint2 hv = *(const uint2*)&sh_h[l * 64 + lane * 2];
        const uint4 a0 = *(const uint4*)&sh_a[l * APADU + mb];
        const uint4 a1 = *(const uint4*)&sh_a[l * APADU + mb + 4];
        const half2 h0 = *(const half2*)&hv.x, h1 = *(const half2*)&hv.y;
        const unsigned int av[8] = {a0.x,a0.y,a0.z,a0.w, a1.x,a1.y,a1.z,a1.w};
#pragma unroll
        for (int i = 0; i < 8; ++i) {
            const half2 a = *(const half2*)&av[i];
            acc[i][0] = __hmax2(acc[i][0], __hadd2(h0, a));
            acc[i][1] = __hmax2(acc[i][1], __hadd2(h1, a));
        }
    }

    // ---- write fp16 partials [sp][b][m][d], coalesced 8B/thread ----
    unsigned short* op = g_scratch + (((size_t)sp * BB + b) * MM + m0 + mb) * DD + d0 + lane * 4;
#pragma unroll
    for (int i = 0; i < 8; ++i) {
        uint2 o;
        o.x = *(const unsigned int*)&acc[i][0];
        o.y = *(const unsigned int*)&acc[i][1];
        *(uint2*)(op + (size_t)i * DD) = o;
    }
}

#define TOTU4 (BB * MM * DD / 8)    // 49152 uint4 (8 fp16 each)

__global__ __launch_bounds__(256, 1)
void mr_combine(float* __restrict__ out)
{
    const int t = blockIdx.x * 256 + threadIdx.x;    // 0..49151
    const uint4* s = (const uint4*)g_scratch;

    uint4 v[LSPLIT];
#pragma unroll
    for (int sp = 0; sp < LSPLIT; ++sp)              // MLP 6 x LDG.128
        v[sp] = s[(size_t)sp * TOTU4 + t];

    half2 r0 = *(const half2*)&v[0].x;
    half2 r1 = *(const half2*)&v[0].y;
    half2 r2 = *(const half2*)&v[0].z;
    half2 r3 = *(const half2*)&v[0].w;
#pragma unroll
    for (int sp = 1; sp < LSPLIT; ++sp) {
        r0 = __hmax2(r0, *(const half2*)&v[sp].x);
        r1 = __hmax2(r1, *(const half2*)&v[sp].y);
        r2 = __hmax2(r2, *(const half2*)&v[sp].z);
        r3 = __hmax2(r3, *(const half2*)&v[sp].w);
    }
    const float2 f0 = __half22float2(r0);
    const float2 f1 = __half22float2(r1);
    const float2 f2 = __half22float2(r2);
    const float2 f3 = __half22float2(r3);
    float4 o0, o1;
    o0.x = f0.x; o0.y = f0.y; o0.z = f1.x; o0.w = f1.y;
    o1.x = f2.x; o1.y = f2.y; o1.z = f3.x; o1.w = f3.y;
    float4* og = (float4*)out + (size_t)t * 2;
    og[0] = o0;
    og[1] = o1;
}

extern "C" void kernel_launch(void* const* d_in, const int* in_sizes, int n_in,
                              void* d_out, int out_size)
{
    const float* h    = (const float*)d_in[0];
    const int*   mask = (const int*)  d_in[1];
    float*       out  = (float*)d_out;

    cudaFuncSetAttribute(mr_main,
                         cudaFuncAttributeMaxDynamicSharedMemorySize, SMEM_BYTES);

    dim3 grid(DD / 128, LSPLIT * 2, BB);   // 6 x 12 x 4 = 288 blocks, occ 2 (no reg cap)
    mr_main<<<grid, 256, SMEM_BYTES>>>(h, mask);
    mr_combine<<<TOTU4 / 256, 256>>>(out);    // 192 blocks
}